// round 1
// baseline (speedup 1.0000x reference)
#include <cuda_runtime.h>
#include <math.h>

// CollectNeighbourAverageAndMax: out[v] = concat(mean_k x[idx[v,k]], max_k x[idx[v,k]])
// V=100000, K=32, F=64. Inputs: d_in[0] = x [V*F] fp32, d_in[1] = idxs [V*K] int32.
// Output: [V, 2F] fp32.
//
// Strategy: one warp per output row. Lane l loads idx[v][l] (coalesced), then
// __shfl broadcasts each index. Each lane owns 2 features (float2) so a warp
// reads exactly 256B contiguous per neighbor row. K-loop fully unrolled for MLP.
// x (25.6MB) is L2-resident, so this is an L2-bandwidth-bound kernel.

#define VV 100000
#define KK 32
#define FF 64

__global__ __launch_bounds__(256, 8)
void collect_nbr_kernel(const float* __restrict__ x,
                        const int* __restrict__ idxs,
                        float* __restrict__ out) {
    const int warp = (blockIdx.x * blockDim.x + threadIdx.x) >> 5;
    const int lane = threadIdx.x & 31;
    if (warp >= VV) return;

    // Each lane loads one neighbor index for this row (coalesced 128B).
    const int my_idx = __ldg(idxs + (size_t)warp * KK + lane);

    float2 sum = make_float2(0.f, 0.f);
    float2 mx  = make_float2(-INFINITY, -INFINITY);

    const int foff = lane * 2;  // this lane's feature pair

    #pragma unroll
    for (int k = 0; k < KK; k++) {
        const int nb = __shfl_sync(0xffffffffu, my_idx, k);
        const float2 v = __ldg(reinterpret_cast<const float2*>(
            x + (size_t)nb * FF + foff));
        sum.x += v.x;
        sum.y += v.y;
        mx.x = fmaxf(mx.x, v.x);
        mx.y = fmaxf(mx.y, v.y);
    }

    float2* o = reinterpret_cast<float2*>(out + (size_t)warp * (2 * FF));
    o[lane]      = make_float2(sum.x * (1.0f / KK), sum.y * (1.0f / KK));  // mean half
    o[32 + lane] = mx;                                                     // max half
}

extern "C" void kernel_launch(void* const* d_in, const int* in_sizes, int n_in,
                              void* d_out, int out_size) {
    const float* x    = (const float*)d_in[0];
    const int*   idxs = (const int*)d_in[1];
    float*       out  = (float*)d_out;

    // 32 threads (1 warp) per row, 256 threads/block -> 8 rows/block
    const int threads = 256;
    const int rows_per_block = threads / 32;
    const int blocks = (VV + rows_per_block - 1) / rows_per_block;
    collect_nbr_kernel<<<blocks, threads>>>(x, idxs, out);
}